// round 9
// baseline (speedup 1.0000x reference)
#include <cuda_runtime.h>
#include <cuda_bf16.h>

// Batched per-sample MLP: B=32, 1024 -> 2048 (relu) -> 2048 (relu) -> 1024 (linear)
// HBM/LTS-bound GEMV chain pinned at the chip streaming cap (~6.1 TB/s/kernel).
// Round 8: fine-grained cross-layer pipelining. PDL trigger moved to kernel top
// so successor grids launch while producers stream; the coarse grid-dependency
// sync is replaced by per-sample release/acquire counters (done[b]==32), so a
// consumer CTA starts as soon as ITS sample's producers finished. DRAM never
// drains at layer boundaries. Streaming core unchanged from R4.

#define BATCH 32
#define L0 1024
#define L1 2048
#define L2 2048
#define L3 1024

// Per-sample param layout offsets (fp32 elements)
#define W1_OFF 0LL
#define B1_OFF (W1_OFF + (long long)L0 * L1)          // 2097152
#define W2_OFF (B1_OFF + L1)                          // 2099200
#define B2_OFF (W2_OFF + (long long)L1 * L2)          // 6293504
#define W3_OFF (B2_OFF + L2)                          // 6295552
#define B3_OFF (W3_OFF + (long long)L2 * L3)          // 8392704
#define P_LEN  (B3_OFF + L3)                          // 8393728

// Device-global state (zero-initialized at load; every pass restores zeros).
__device__ float g_act1[BATCH * L1];
__device__ float g_act2[BATCH * L2];
__device__ int   g_done1[BATCH];   // layer-1 CTAs finished for sample b (32)
__device__ int   g_rd1[BATCH];     // layer-2 CTAs that staged act1[b]   (32)
__device__ int   g_done2[BATCH];   // layer-2 CTAs finished for sample b (32)
__device__ int   g_rd2[BATCH];     // layer-3 CTAs that staged act2[b]   (32)

__device__ __forceinline__ int ld_acquire_gpu(const int* p) {
    int v;
    asm volatile("ld.acquire.gpu.b32 %0, [%1];" : "=r"(v) : "l"(p) : "memory");
    return v;
}

// LAYER: 1, 2, 3. Producers-per-sample is 32 for every stage.
// ZERO_N: elements of z_buf zeroed by ks==0 CTAs BEFORE the trigger (buffer
// not read by any in-flight producer: act2 for L1, out for L2).
template <int IN, int OUT, int CHUNK, int BLOCK, bool RELU_IN, int LAYER, int ZERO_N>
__global__ void __launch_bounds__(BLOCK)
mlp_layer_pipe(const float* __restrict__ params,
               long long w_off, long long b_off,
               const float* __restrict__ x_in,
               float* __restrict__ y_out,
               float* __restrict__ z_buf)
{
    __shared__ float sx[CHUNK];

    const int b   = blockIdx.y;
    const int ks  = blockIdx.z;
    const int i0  = ks * CHUNK;
    const int o4  = (blockIdx.x * BLOCK + threadIdx.x) * 4;

    // Dependency-free zero job (pre-trigger), then release fence so the
    // zeros are device-visible before the successor grid can launch.
    if (ZERO_N > 0 && ks == 0) {
        const int nz  = gridDim.x * BATCH;
        const int cid = blockIdx.y * gridDim.x + blockIdx.x;
        float4* zb = reinterpret_cast<float4*>(z_buf);
        const int total4 = ZERO_N / 4;
        for (int idx = cid * BLOCK + threadIdx.x; idx < total4; idx += nz * BLOCK)
            zb[idx] = make_float4(0.f, 0.f, 0.f, 0.f);
        __threadfence();
    }

    // Bias prefetch (pure input, independent of producers).
    float ax = 0.f, ay = 0.f, az = 0.f, aw = 0.f;
    if (ks == 0) {
        const float* __restrict__ Bv = params + (long long)b * P_LEN + b_off + o4;
        float4 bv = __ldg(reinterpret_cast<const float4*>(Bv));
        ax = bv.x; ay = bv.y; az = bv.z; aw = bv.w;
    }

#if defined(__CUDA_ARCH__) && (__CUDA_ARCH__ >= 900)
    // Early trigger: successor grid may launch now. Deadlock-free: PSS only
    // launches the successor after ALL CTAs of this grid executed the trigger,
    // so producers are fully resident before any consumer takes a slot.
    if (LAYER < 3) cudaTriggerProgrammaticLaunchCompletion();
#endif

    // Wait for THIS sample's producers (fine-grained, not whole-grid).
    if (LAYER == 2) {
        if (threadIdx.x == 0)
            while (ld_acquire_gpu(&g_done1[b]) < 32) __nanosleep(128);
        __syncthreads();
    } else if (LAYER == 3) {
        if (threadIdx.x == 0)
            while (ld_acquire_gpu(&g_done2[b]) < 32) __nanosleep(128);
        __syncthreads();
    }

    // Stage this CTA's input chunk, applying relu if needed.
    const float* __restrict__ xb = x_in + (long long)b * IN + i0;
    for (int i = threadIdx.x; i < CHUNK; i += BLOCK) {
        float v = __ldg(&xb[i]);
        if (RELU_IN) v = fmaxf(v, 0.0f);
        sx[i] = v;
    }
    __syncthreads();

    // Mark activation chunk consumed (release) — enables act1 recycling.
    if (LAYER == 2 && threadIdx.x == 0) { __threadfence(); atomicAdd(&g_rd1[b], 1); }
    if (LAYER == 3 && threadIdx.x == 0) { __threadfence(); atomicAdd(&g_rd2[b], 1); }

    const float* __restrict__ Wb =
        params + (long long)b * P_LEN + w_off + (long long)i0 * OUT + o4;

    // Inner loop: one LDG.128 per thread per i (512B/warp), 8-deep unroll for MLP.
    #pragma unroll 8
    for (int i = 0; i < CHUNK; ++i) {
        float4 w = __ldg(reinterpret_cast<const float4*>(Wb + (long long)i * OUT));
        float s = sx[i];
        ax = fmaf(s, w.x, ax);
        ay = fmaf(s, w.y, ay);
        az = fmaf(s, w.z, az);
        aw = fmaf(s, w.w, aw);
    }

    float* y = y_out + (long long)b * OUT + o4;
    atomicAdd(y + 0, ax);
    atomicAdd(y + 1, ay);
    atomicAdd(y + 2, az);
    atomicAdd(y + 3, aw);

    __syncthreads();  // all threads' atomics ordered before the flag release

    if (LAYER == 1 && threadIdx.x == 0) { __threadfence(); atomicAdd(&g_done1[b], 1); }
    if (LAYER == 2 && threadIdx.x == 0) { __threadfence(); atomicAdd(&g_done2[b], 1); }

    // Layer-3 tail jobs: recycle buffers/flags for the next graph replay.
    if (LAYER == 3 && ks == 0) {
        // act1[b] fully consumed when all 32 layer-2 CTAs staged it.
        if (threadIdx.x == 0)
            while (ld_acquire_gpu(&g_rd1[b]) < 32) __nanosleep(128);
        __syncthreads();
        float4* zb = reinterpret_cast<float4*>(&g_act1[(long long)b * L1]);
        for (int idx = threadIdx.x; idx < L1 / 4; idx += BLOCK)
            zb[idx] = make_float4(0.f, 0.f, 0.f, 0.f);
        __syncthreads();
        if (threadIdx.x == 0) { g_done1[b] = 0; g_rd1[b] = 0; }
    }
    if (LAYER == 3 && ks == 1) {
        if (threadIdx.x == 0) {
            while (ld_acquire_gpu(&g_rd2[b]) < 32) __nanosleep(128);
            g_done2[b] = 0; g_rd2[b] = 0;
        }
    }
}

extern "C" void kernel_launch(void* const* d_in, const int* in_sizes, int n_in,
                              void* d_out, int out_size)
{
    const float* params = (const float*)d_in[0];  // (B, P) fp32
    const float* x      = (const float*)d_in[1];  // (B, 1024) fp32
    float* out          = (float*)d_out;          // (B, 1024) fp32

    float* act1;
    float* act2;
    cudaGetSymbolAddress((void**)&act1, g_act1);
    cudaGetSymbolAddress((void**)&act2, g_act2);

    cudaLaunchAttribute pdl_attr[1];
    pdl_attr[0].id = cudaLaunchAttributeProgrammaticStreamSerialization;
    pdl_attr[0].val.programmaticStreamSerializationAllowed = 1;

    // Layer 1: 1024 -> 2048. grid (2, 32, 16) = 1024 CTAs. ks==0 zeroes act2.
    {
        dim3 grid(L1 / (256 * 4), BATCH, L0 / 64);
        auto kfn = mlp_layer_pipe<L0, L1, 64, 256, false, 1, BATCH * L2>;
        kfn<<<grid, 256>>>(params, W1_OFF, B1_OFF, x, act1, act2);
    }
    // Layer 2: 2048 -> 2048. grid (2, 32, 16) = 1024 CTAs, chunk 128.
    // ks==0 zeroes `out`. Polls done1[b]. PDL successor of layer 1.
    {
        cudaLaunchConfig_t cfg = {};
        cfg.gridDim  = dim3(L2 / (256 * 4), BATCH, L1 / 128);
        cfg.blockDim = dim3(256, 1, 1);
        cfg.attrs = pdl_attr;
        cfg.numAttrs = 1;
        auto kfn = mlp_layer_pipe<L1, L2, 128, 256, true, 2, BATCH * L3>;
        cudaLaunchKernelEx(&cfg, kfn, params, W2_OFF, B2_OFF,
                           (const float*)act1, act2, out);
    }
    // Layer 3: 2048 -> 1024. grid (1, 32, 32) = 1024 CTAs, chunk 64.
    // Polls done2[b]; ks==0/1 recycle act1 + flags. PDL successor of layer 2.
    {
        cudaLaunchConfig_t cfg = {};
        cfg.gridDim  = dim3(L3 / (256 * 4), BATCH, L2 / 64);
        cfg.blockDim = dim3(256, 1, 1);
        cfg.attrs = pdl_attr;
        cfg.numAttrs = 1;
        auto kfn = mlp_layer_pipe<L2, L3, 64, 256, true, 3, 0>;
        cudaLaunchKernelEx(&cfg, kfn, params, W3_OFF, B3_OFF,
                           (const float*)act2, out, nullptr);
    }
}

// round 10
// speedup vs baseline: 1.0657x; 1.0657x over previous
#include <cuda_runtime.h>
#include <cuda_bf16.h>

// Batched per-sample MLP: B=32, 1024 -> 2048 (relu) -> 2048 (relu) -> 1024 (linear)
// HBM-bound GEMV chain at the achievable streaming ceiling (~6.1 TB/s per kernel).
// Round 9: revert to R7 structure (best: 162.6us) — coarse PDL chaining, zero
// jobs fused into ks==0 CTAs, no memset nodes — plus one change: weight loads
// use __ldcs (evict-first streaming) since W has zero reuse, keeping L2 for
// activations/bias/atomics.

#define BATCH 32
#define L0 1024
#define L1 2048
#define L2 2048
#define L3 1024

// Per-sample param layout offsets (fp32 elements)
#define W1_OFF 0LL
#define B1_OFF (W1_OFF + (long long)L0 * L1)          // 2097152
#define W2_OFF (B1_OFF + L1)                          // 2099200
#define B2_OFF (W2_OFF + (long long)L1 * L2)          // 6293504
#define W3_OFF (B2_OFF + L2)                          // 6295552
#define B3_OFF (W3_OFF + (long long)L2 * L3)          // 8392704
#define P_LEN  (B3_OFF + L3)                          // 8393728

// Intermediate activations (device globals — zero-initialized at load,
// re-zeroed each pass for graph replay correctness).
__device__ float g_act1[BATCH * L1];
__device__ float g_act2[BATCH * L2];

// One CTA: BLOCK threads, each computing 4 consecutive outputs over a CHUNK of
// the input dimension; partial sums accumulated into y via atomicAdd.
// RELU_IN : apply relu to x_in while staging (x_in holds pre-activation sums).
// ZERO_N  : element count of z_buf for ks==0 CTAs to zero.
// PDL     : call cudaGridDependencySynchronize() before touching x_in.
// ZERO_POST: zero z_buf AFTER the dependency sync (z_buf is read by the
//            predecessor, so the zero must wait for it — layer3 zeroing act1).
template <int IN, int OUT, int CHUNK, int BLOCK, bool RELU_IN, int ZERO_N,
          bool PDL, bool ZERO_POST>
__global__ void __launch_bounds__(BLOCK)
mlp_layer_splitk(const float* __restrict__ params,
                 long long w_off, long long b_off,
                 const float* __restrict__ x_in,
                 float* __restrict__ y_out,
                 float* __restrict__ z_buf)
{
    __shared__ float sx[CHUNK];

    const int b   = blockIdx.y;
    const int ks  = blockIdx.z;
    const int i0  = ks * CHUNK;
    const int o4  = (blockIdx.x * BLOCK + threadIdx.x) * 4;

    const int nzeroers = gridDim.x * BATCH;
    const int cta_id   = blockIdx.y * gridDim.x + blockIdx.x;

    // Pre-sync side job: zero a buffer the predecessor does NOT read
    // (runs during the predecessor's drain wave under PDL).
    if (ZERO_N > 0 && !ZERO_POST && ks == 0) {
        float4* zb = reinterpret_cast<float4*>(z_buf);
        const int total4 = ZERO_N / 4;
        for (int idx = cta_id * BLOCK + threadIdx.x; idx < total4;
             idx += nzeroers * BLOCK)
            zb[idx] = make_float4(0.f, 0.f, 0.f, 0.f);
    }

    // Pre-sync: bias prefetch (pure input, independent of predecessor).
    float ax = 0.f, ay = 0.f, az = 0.f, aw = 0.f;
    if (ks == 0) {
        const float* __restrict__ Bv = params + (long long)b * P_LEN + b_off + o4;
        float4 bv = __ldg(reinterpret_cast<const float4*>(Bv));
        ax = bv.x; ay = bv.y; az = bv.z; aw = bv.w;
    }

#if defined(__CUDA_ARCH__) && (__CUDA_ARCH__ >= 900)
    if (PDL) cudaGridDependencySynchronize();
#endif

    // Post-sync zero job (buffer was read by the predecessor; sync makes it safe).
    if (ZERO_N > 0 && ZERO_POST && ks == 0) {
        float4* zb = reinterpret_cast<float4*>(z_buf);
        const int total4 = ZERO_N / 4;
        for (int idx = cta_id * BLOCK + threadIdx.x; idx < total4;
             idx += nzeroers * BLOCK)
            zb[idx] = make_float4(0.f, 0.f, 0.f, 0.f);
    }

    // Stage this CTA's input chunk, applying relu if needed.
    const float* __restrict__ xb = x_in + (long long)b * IN + i0;
    for (int i = threadIdx.x; i < CHUNK; i += BLOCK) {
        float v = __ldg(&xb[i]);
        if (RELU_IN) v = fmaxf(v, 0.0f);
        sx[i] = v;
    }
    __syncthreads();

    const float* __restrict__ Wb =
        params + (long long)b * P_LEN + w_off + (long long)i0 * OUT + o4;

    // Inner loop: one streaming LDG.128 per thread per i (512B/warp).
    // __ldcs: W is read exactly once — evict-first keeps L2 for act/bias/atomics.
    #pragma unroll 8
    for (int i = 0; i < CHUNK; ++i) {
        float4 w = __ldcs(reinterpret_cast<const float4*>(Wb + (long long)i * OUT));
        float s = sx[i];
        ax = fmaf(s, w.x, ax);
        ay = fmaf(s, w.y, ay);
        az = fmaf(s, w.z, az);
        aw = fmaf(s, w.w, aw);
    }

    float* y = y_out + (long long)b * OUT + o4;
    atomicAdd(y + 0, ax);
    atomicAdd(y + 1, ay);
    atomicAdd(y + 2, az);
    atomicAdd(y + 3, aw);

#if defined(__CUDA_ARCH__) && (__CUDA_ARCH__ >= 900)
    // Let the dependent kernel launch as soon as all CTAs reach here.
    cudaTriggerProgrammaticLaunchCompletion();
#endif
}

extern "C" void kernel_launch(void* const* d_in, const int* in_sizes, int n_in,
                              void* d_out, int out_size)
{
    const float* params = (const float*)d_in[0];  // (B, P) fp32
    const float* x      = (const float*)d_in[1];  // (B, 1024) fp32
    float* out          = (float*)d_out;          // (B, 1024) fp32

    float* act1;
    float* act2;
    cudaGetSymbolAddress((void**)&act1, g_act1);
    cudaGetSymbolAddress((void**)&act2, g_act2);

    // No memsets: act1/act2 are zero at load and re-zeroed each pass
    // (layer3 zeroes act1 post-sync, layer1 zeroes act2, layer2 zeroes out).

    cudaLaunchAttribute pdl_attr[1];
    pdl_attr[0].id = cudaLaunchAttributeProgrammaticStreamSerialization;
    pdl_attr[0].val.programmaticStreamSerializationAllowed = 1;

    // Layer 1: 1024 -> 2048. tiles=2, KS=16 (chunk 64) -> 1024 CTAs.
    // ks==0 CTAs also zero act2. No PDL (first kernel).
    {
        dim3 grid(L1 / (256 * 4), BATCH, L0 / 64);
        auto kfn = mlp_layer_splitk<L0, L1, 64, 256, false, BATCH * L2, false, false>;
        kfn<<<grid, 256>>>(params, W1_OFF, B1_OFF, x, act1, act2);
    }
    // Layer 2: 2048 -> 2048. tiles=2, KS=16 (chunk 128) -> 1024 CTAs. relu on read.
    // ks==0 CTAs zero `out` pre-sync. PDL on layer 1.
    {
        cudaLaunchConfig_t cfg = {};
        cfg.gridDim  = dim3(L2 / (256 * 4), BATCH, L1 / 128);
        cfg.blockDim = dim3(256, 1, 1);
        cfg.attrs = pdl_attr;
        cfg.numAttrs = 1;
        auto kfn = mlp_layer_splitk<L1, L2, 128, 256, true, BATCH * L3, true, false>;
        cudaLaunchKernelEx(&cfg, kfn, params, W2_OFF, B2_OFF,
                           (const float*)act1, act2, out);
    }
    // Layer 3: 2048 -> 1024. tiles=1, KS=32 (chunk 64) -> 1024 CTAs. relu on read.
    // ks==0 CTAs zero act1 POST-sync (act1 is read by layer 2). PDL on layer 2.
    {
        cudaLaunchConfig_t cfg = {};
        cfg.gridDim  = dim3(L3 / (256 * 4), BATCH, L2 / 64);
        cfg.blockDim = dim3(256, 1, 1);
        cfg.attrs = pdl_attr;
        cfg.numAttrs = 1;
        auto kfn = mlp_layer_splitk<L2, L3, 64, 256, true, BATCH * L1, true, true>;
        cudaLaunchKernelEx(&cfg, kfn, params, W3_OFF, B3_OFF,
                           (const float*)act2, out, act1);
    }
}

// round 12
// speedup vs baseline: 1.0745x; 1.0083x over previous
#include <cuda_runtime.h>
#include <cuda_bf16.h>

// Batched per-sample MLP: B=32, 1024 -> 2048 (relu) -> 2048 (relu) -> 1024 (linear)
// HBM-bound GEMV chain at the achievable streaming ceiling (~6.1 TB/s per kernel).
// Round 11: exact revert to the verified R9 structure (best: 159.8us) — coarse
// PDL chaining, zero jobs fused into ks==0 CTAs, no memset nodes, __ldcs weight
// streaming — with ONE change: weight-loop unroll 8 -> 16 for deeper LDG batching.

#define BATCH 32
#define L0 1024
#define L1 2048
#define L2 2048
#define L3 1024

// Per-sample param layout offsets (fp32 elements)
#define W1_OFF 0LL
#define B1_OFF (W1_OFF + (long long)L0 * L1)          // 2097152
#define W2_OFF (B1_OFF + L1)                          // 2099200
#define B2_OFF (W2_OFF + (long long)L1 * L2)          // 6293504
#define W3_OFF (B2_OFF + L2)                          // 6295552
#define B3_OFF (W3_OFF + (long long)L2 * L3)          // 8392704
#define P_LEN  (B3_OFF + L3)                          // 8393728

// Intermediate activations (device globals — zero-initialized at load,
// re-zeroed each pass for graph replay correctness).
__device__ float g_act1[BATCH * L1];
__device__ float g_act2[BATCH * L2];

// One CTA: BLOCK threads, each computing 4 consecutive outputs over a CHUNK of
// the input dimension; partial sums accumulated into y via atomicAdd.
// RELU_IN : apply relu to x_in while staging (x_in holds pre-activation sums).
// ZERO_N  : element count of z_buf for ks==0 CTAs to zero.
// PDL     : call cudaGridDependencySynchronize() before touching x_in.
// ZERO_POST: zero z_buf AFTER the dependency sync (z_buf is read by the
//            predecessor, so the zero must wait for it — layer3 zeroing act1).
template <int IN, int OUT, int CHUNK, int BLOCK, bool RELU_IN, int ZERO_N,
          bool PDL, bool ZERO_POST>
__global__ void __launch_bounds__(BLOCK)
mlp_layer_splitk(const float* __restrict__ params,
                 long long w_off, long long b_off,
                 const float* __restrict__ x_in,
                 float* __restrict__ y_out,
                 float* __restrict__ z_buf)
{
    __shared__ float sx[CHUNK];

    const int b   = blockIdx.y;
    const int ks  = blockIdx.z;
    const int i0  = ks * CHUNK;
    const int o4  = (blockIdx.x * BLOCK + threadIdx.x) * 4;

    const int nzeroers = gridDim.x * BATCH;
    const int cta_id   = blockIdx.y * gridDim.x + blockIdx.x;

    // Pre-sync side job: zero a buffer the predecessor does NOT read
    // (runs during the predecessor's drain wave under PDL).
    if (ZERO_N > 0 && !ZERO_POST && ks == 0) {
        float4* zb = reinterpret_cast<float4*>(z_buf);
        const int total4 = ZERO_N / 4;
        for (int idx = cta_id * BLOCK + threadIdx.x; idx < total4;
             idx += nzeroers * BLOCK)
            zb[idx] = make_float4(0.f, 0.f, 0.f, 0.f);
    }

    // Pre-sync: bias prefetch (pure input, independent of predecessor).
    float ax = 0.f, ay = 0.f, az = 0.f, aw = 0.f;
    if (ks == 0) {
        const float* __restrict__ Bv = params + (long long)b * P_LEN + b_off + o4;
        float4 bv = __ldg(reinterpret_cast<const float4*>(Bv));
        ax = bv.x; ay = bv.y; az = bv.z; aw = bv.w;
    }

#if defined(__CUDA_ARCH__) && (__CUDA_ARCH__ >= 900)
    if (PDL) cudaGridDependencySynchronize();
#endif

    // Post-sync zero job (buffer was read by the predecessor; sync makes it safe).
    if (ZERO_N > 0 && ZERO_POST && ks == 0) {
        float4* zb = reinterpret_cast<float4*>(z_buf);
        const int total4 = ZERO_N / 4;
        for (int idx = cta_id * BLOCK + threadIdx.x; idx < total4;
             idx += nzeroers * BLOCK)
            zb[idx] = make_float4(0.f, 0.f, 0.f, 0.f);
    }

    // Stage this CTA's input chunk, applying relu if needed.
    const float* __restrict__ xb = x_in + (long long)b * IN + i0;
    for (int i = threadIdx.x; i < CHUNK; i += BLOCK) {
        float v = __ldg(&xb[i]);
        if (RELU_IN) v = fmaxf(v, 0.0f);
        sx[i] = v;
    }
    __syncthreads();

    const float* __restrict__ Wb =
        params + (long long)b * P_LEN + w_off + (long long)i0 * OUT + o4;

    // Inner loop: one streaming LDG.128 per thread per i (512B/warp).
    // __ldcs: W is read exactly once — evict-first keeps L2 for act/bias/atomics.
    // 16-deep unroll for a deeper front-batched LDG window.
    #pragma unroll 16
    for (int i = 0; i < CHUNK; ++i) {
        float4 w = __ldcs(reinterpret_cast<const float4*>(Wb + (long long)i * OUT));
        float s = sx[i];
        ax = fmaf(s, w.x, ax);
        ay = fmaf(s, w.y, ay);
        az = fmaf(s, w.z, az);
        aw = fmaf(s, w.w, aw);
    }

    float* y = y_out + (long long)b * OUT + o4;
    atomicAdd(y + 0, ax);
    atomicAdd(y + 1, ay);
    atomicAdd(y + 2, az);
    atomicAdd(y + 3, aw);

#if defined(__CUDA_ARCH__) && (__CUDA_ARCH__ >= 900)
    // Let the dependent kernel launch as soon as all CTAs reach here.
    cudaTriggerProgrammaticLaunchCompletion();
#endif
}

extern "C" void kernel_launch(void* const* d_in, const int* in_sizes, int n_in,
                              void* d_out, int out_size)
{
    const float* params = (const float*)d_in[0];  // (B, P) fp32
    const float* x      = (const float*)d_in[1];  // (B, 1024) fp32
    float* out          = (float*)d_out;          // (B, 1024) fp32

    float* act1;
    float* act2;
    cudaGetSymbolAddress((void**)&act1, g_act1);
    cudaGetSymbolAddress((void**)&act2, g_act2);

    // No memsets: act1/act2 are zero at load and re-zeroed each pass
    // (layer3 zeroes act1 post-sync, layer1 zeroes act2, layer2 zeroes out).

    cudaLaunchAttribute pdl_attr[1];
    pdl_attr[0].id = cudaLaunchAttributeProgrammaticStreamSerialization;
    pdl_attr[0].val.programmaticStreamSerializationAllowed = 1;

    // Layer 1: 1024 -> 2048. tiles=2, KS=16 (chunk 64) -> 1024 CTAs.
    // ks==0 CTAs also zero act2. No PDL (first kernel).
    {
        dim3 grid(L1 / (256 * 4), BATCH, L0 / 64);
        auto kfn = mlp_layer_splitk<L0, L1, 64, 256, false, BATCH * L2, false, false>;
        kfn<<<grid, 256>>>(params, W1_OFF, B1_OFF, x, act1, act2);
    }
    // Layer 2: 2048 -> 2048. tiles=2, KS=16 (chunk 128) -> 1024 CTAs. relu on read.
    // ks==0 CTAs zero `out` pre-sync. PDL on layer 1.
    {
        cudaLaunchConfig_t cfg = {};
        cfg.gridDim  = dim3(L2 / (256 * 4), BATCH, L1 / 128);
        cfg.blockDim = dim3(256, 1, 1);
        cfg.attrs = pdl_attr;
        cfg.numAttrs = 1;
        auto kfn = mlp_layer_splitk<L1, L2, 128, 256, true, BATCH * L3, true, false>;
        cudaLaunchKernelEx(&cfg, kfn, params, W2_OFF, B2_OFF,
                           (const float*)act1, act2, out);
    }
    // Layer 3: 2048 -> 1024. tiles=1, KS=32 (chunk 64) -> 1024 CTAs. relu on read.
    // ks==0 CTAs zero act1 POST-sync (act1 is read by layer 2). PDL on layer 2.
    {
        cudaLaunchConfig_t cfg = {};
        cfg.gridDim  = dim3(L3 / (256 * 4), BATCH, L2 / 64);
        cfg.blockDim = dim3(256, 1, 1);
        cfg.attrs = pdl_attr;
        cfg.numAttrs = 1;
        auto kfn = mlp_layer_splitk<L2, L3, 64, 256, true, BATCH * L1, true, true>;
        cudaLaunchKernelEx(&cfg, kfn, params, W3_OFF, B3_OFF,
                           (const float*)act2, out, act1);
    }
}